// round 10
// baseline (speedup 1.0000x reference)
#include <cuda_runtime.h>
#include <cuda_bf16.h>
#include <cstdint>

#define N_ATOMS 50000
#define N_BONDS 100000
#define NE      (2 * N_BONDS)       // 200000 directed edges
#define HIDDEN  300
#define ATOM_DIM 133
#define BOND_DIM 14
#define N_MOL   2048
#define FEAT_DIM 200
#define DEPTH   3
#define OUT_COLS (HIDDEN + FEAT_DIM)  // 500

#define NPAD    320                 // padded N (2 x 160)
#define KPAD_I  192                 // mode 0: K=147
#define KPAD_M  320                 // mode 3: K=300
#define KPAD_A  448                 // mode 2: K=433

// ---------------- scratch (device globals; no allocation allowed) ----------
__device__ float g_h0 [(size_t)NE * HIDDEN];
__device__ float g_hA [(size_t)NE * HIDDEN];
__device__ float g_hB [(size_t)NE * HIDDEN];
__device__ float g_inc[(size_t)N_ATOMS * HIDDEN];
// pre-split weights, layout [NPAD][Kpad] bf16 (B[n][k] = W[k][n]), zero-padded
__device__ __nv_bfloat16 g_Wi_hi[NPAD * KPAD_I];
__device__ __nv_bfloat16 g_Wi_lo[NPAD * KPAD_I];
__device__ __nv_bfloat16 g_Wm_hi[NPAD * KPAD_M];
__device__ __nv_bfloat16 g_Wm_lo[NPAD * KPAD_M];
__device__ __nv_bfloat16 g_Wa_hi[NPAD * KPAD_A];
__device__ __nv_bfloat16 g_Wa_lo[NPAD * KPAD_A];

// ============================ PTX helpers (sm_80+) ==========================
__device__ __forceinline__ uint32_t smem_u32(const void* p) {
    uint32_t a;
    asm("{ .reg .u64 t; cvta.to.shared.u64 t, %1; cvt.u32.u64 %0, t; }"
        : "=r"(a) : "l"(p));
    return a;
}
__device__ __forceinline__ void ldm_x4(uint32_t* r, uint32_t addr) {
    asm volatile("ldmatrix.sync.aligned.m8n8.x4.shared.b16 {%0,%1,%2,%3}, [%4];"
                 : "=r"(r[0]), "=r"(r[1]), "=r"(r[2]), "=r"(r[3]) : "r"(addr));
}
__device__ __forceinline__ void ldm_x2(uint32_t* r, uint32_t addr) {
    asm volatile("ldmatrix.sync.aligned.m8n8.x2.shared.b16 {%0,%1}, [%2];"
                 : "=r"(r[0]), "=r"(r[1]) : "r"(addr));
}
__device__ __forceinline__ void mma_bf16(float* c, const uint32_t* a,
                                         const uint32_t* b) {
    asm volatile(
        "mma.sync.aligned.m16n8k16.row.col.f32.bf16.bf16.f32 "
        "{%0,%1,%2,%3}, {%4,%5,%6,%7}, {%8,%9}, {%0,%1,%2,%3};"
        : "+f"(c[0]), "+f"(c[1]), "+f"(c[2]), "+f"(c[3])
        : "r"(a[0]), "r"(a[1]), "r"(a[2]), "r"(a[3]), "r"(b[0]), "r"(b[1]));
}

// ===================== SMEM layout (padded rows, 144 B) =====================
#define ROWB    144                 // 72 bf16 per row (64 data + 8 pad)
#define SM_AHI  0                   // 128 x 144 = 18432
#define SM_ALO  18432
#define SM_BHI  36864               // 160 x 144 = 23040
#define SM_BLO  59904
#define SMEM_TOTAL 82944

// ============================================================================
// Split-bf16 HMMA GEMM: out[r,0:300] = relu(A(r,:) @ W + bias (+ resid))
//   mode 0: A(r,k)= k<14 ? edge_attr[r*14+k] : x[src[r]*133+k-14]    (K=147)
//   mode 2: A(r,k)= k<133? x[r*133+k]        : m_v[r*300+k-133]      (K=433)
//   mode 3: A(r,k)= inc[src[r]*300+k] - h[rev[r]*300+k]              (K=300)
// D = Ahi@Bhi + Ahi@Blo + Alo@Bhi  (fp32 accum), B[n][k]=W[k][n].
// BM=128, BN=160, BK=64; 512 threads = 16 warps (4M x 4N), warp tile 32x40.
// ============================================================================
__global__ __launch_bounds__(512)
void mma_gemm(int mode, int rows, int K, int Kpad,
              const float* __restrict__ G0,
              const float* __restrict__ G1,
              const int*   __restrict__ gidx,
              const int*   __restrict__ gidx2,
              const __nv_bfloat16* __restrict__ Whi,
              const __nv_bfloat16* __restrict__ Wlo,
              const float* __restrict__ bias,
              const float* __restrict__ resid,
              float* __restrict__ out)
{
    extern __shared__ char smem[];
    const uint32_t sb = smem_u32(smem);
    const int tid  = threadIdx.x;
    const int wid  = tid >> 5;
    const int lane = tid & 31;
    const int warp_m = wid & 3;        // 0..3 -> rows warp_m*32
    const int warp_n = wid >> 2;       // 0..3 -> cols warp_n*40
    const int m0  = blockIdx.x * 128;
    const int n0g = blockIdx.y * 160;

    // ldmatrix per-lane base offsets
    const uint32_t aOff = (uint32_t)(warp_m * 32 + (lane & 15)) * ROWB
                        + (uint32_t)((lane >> 4) * 16);          // khalf*2B
    const uint32_t bOff = (uint32_t)(warp_n * 40 + (lane & 7)) * ROWB
                        + (uint32_t)(((lane >> 3) & 1) * 16);
    const uint32_t aHi = sb + SM_AHI + aOff, aLo = sb + SM_ALO + aOff;
    const uint32_t bHi = sb + SM_BHI + bOff, bLo = sb + SM_BLO + bOff;

    float acc[2][5][4];
#pragma unroll
    for (int i = 0; i < 2; i++)
#pragma unroll
        for (int j = 0; j < 5; j++)
#pragma unroll
            for (int q = 0; q < 4; q++) acc[i][j][q] = 0.f;

    // staging indices
    const int sr   = tid >> 2;          // 0..127 row
    const int part = tid & 3;           // 16-k segment
    const int row  = m0 + sr;

    const int nch = Kpad >> 6;
    for (int c = 0; c < nch; c++) {
        const int k0 = c * 64;

        // ---------------- stage A hi/lo (128 x 64) ----------------
        char* arowH = smem + SM_AHI + sr * ROWB + part * 32;
        char* arowL = smem + SM_ALO + sr * ROWB + part * 32;
        if (mode == 3) {
            if (row < rows) {
                int s  = gidx[row];
                int rv = gidx2[row];
                const float* P = &G0[(size_t)s  * HIDDEN + k0 + part * 16];
                const float* Q = &G1[(size_t)rv * HIDDEN + k0 + part * 16];
#pragma unroll
                for (int q = 0; q < 4; q++) {
                    int kg = k0 + part * 16 + q * 4;
                    float4 v = make_float4(0.f, 0.f, 0.f, 0.f);
                    if (kg + 4 <= K) {
                        float4 p = *(const float4*)(P + q * 4);
                        float4 z = *(const float4*)(Q + q * 4);
                        v = make_float4(p.x - z.x, p.y - z.y, p.z - z.z, p.w - z.w);
                    }
                    __nv_bfloat16 hx = __float2bfloat16(v.x);
                    __nv_bfloat16 hy = __float2bfloat16(v.y);
                    __nv_bfloat16 hz = __float2bfloat16(v.z);
                    __nv_bfloat16 hw = __float2bfloat16(v.w);
                    __nv_bfloat162 h01; h01.x = hx; h01.y = hy;
                    __nv_bfloat162 h23; h23.x = hz; h23.y = hw;
                    __nv_bfloat162 l01;
                    l01.x = __float2bfloat16(v.x - __bfloat162float(hx));
                    l01.y = __float2bfloat16(v.y - __bfloat162float(hy));
                    __nv_bfloat162 l23;
                    l23.x = __float2bfloat16(v.z - __bfloat162float(hz));
                    l23.y = __float2bfloat16(v.w - __bfloat162float(hw));
                    *(__nv_bfloat162*)(arowH + q * 8)     = h01;
                    *(__nv_bfloat162*)(arowH + q * 8 + 4) = h23;
                    *(__nv_bfloat162*)(arowL + q * 8)     = l01;
                    *(__nv_bfloat162*)(arowL + q * 8 + 4) = l23;
                }
            } else {
#pragma unroll
                for (int q = 0; q < 4; q++) {
                    *(uint2*)(arowH + q * 8) = make_uint2(0u, 0u);
                    *(uint2*)(arowL + q * 8) = make_uint2(0u, 0u);
                }
            }
        } else {
            int s = 0;
            if (mode == 0 && row < rows) s = gidx[row];
#pragma unroll 4
            for (int q = 0; q < 16; q++) {
                int kg = k0 + part * 16 + q;
                float v = 0.f;
                if (row < rows) {
                    if (mode == 0) {
                        if (kg < BOND_DIM)  v = G0[(size_t)row * BOND_DIM + kg];
                        else if (kg < K)    v = G1[(size_t)s * ATOM_DIM + (kg - BOND_DIM)];
                    } else { // mode 2
                        if (kg < ATOM_DIM)  v = G0[(size_t)row * ATOM_DIM + kg];
                        else if (kg < K)    v = G1[(size_t)row * HIDDEN + (kg - ATOM_DIM)];
                    }
                }
                __nv_bfloat16 h = __float2bfloat16(v);
                *(__nv_bfloat16*)(arowH + q * 2) = h;
                *(__nv_bfloat16*)(arowL + q * 2) =
                    __float2bfloat16(v - __bfloat162float(h));
            }
        }

        // ---------------- stage B hi/lo (160 x 64): uint4 copies ----------
        for (int u = tid; u < 1280; u += 512) {
            int n = u >> 3, q = u & 7;
            char* dst = smem + n * ROWB + q * 16;
            size_t gi = (size_t)(n0g + n) * Kpad + k0 + q * 8;
            *(uint4*)(dst + SM_BHI) = *(const uint4*)&Whi[gi];
            *(uint4*)(dst + SM_BLO) = *(const uint4*)&Wlo[gi];
        }
        __syncthreads();

        // ---------------- mainloop: 4 k16 steps ----------------
#pragma unroll 1
        for (int ks = 0; ks < 4; ks++) {
            const uint32_t ko = (uint32_t)ks * 32;
            uint32_t ah0[4], ah1[4], al0[4], al1[4];
            ldm_x4(ah0, aHi + ko);
            ldm_x4(ah1, aHi + 16 * ROWB + ko);
            ldm_x4(al0, aLo + ko);
            ldm_x4(al1, aLo + 16 * ROWB + ko);
#pragma unroll
            for (int nf = 0; nf < 5; nf++) {
                uint32_t bh[2], bl[2];
                ldm_x2(bh, bHi + nf * (8 * ROWB) + ko);
                ldm_x2(bl, bLo + nf * (8 * ROWB) + ko);
                mma_bf16(acc[0][nf], ah0, bh);
                mma_bf16(acc[0][nf], ah0, bl);
                mma_bf16(acc[0][nf], al0, bh);
                mma_bf16(acc[1][nf], ah1, bh);
                mma_bf16(acc[1][nf], ah1, bl);
                mma_bf16(acc[1][nf], al1, bh);
            }
        }
        __syncthreads();
    }

    // ---------------- epilogue: bias (+resid) + relu ----------------
    const int group = lane >> 2, tig = lane & 3;
#pragma unroll
    for (int mf = 0; mf < 2; mf++) {
#pragma unroll
        for (int nf = 0; nf < 5; nf++) {
            int col = n0g + warp_n * 40 + nf * 8 + tig * 2;
            if (col >= HIDDEN) continue;
            float2 bv = *(const float2*)&bias[col];
#pragma unroll
            for (int half = 0; half < 2; half++) {
                int r = m0 + warp_m * 32 + mf * 16 + group + half * 8;
                if (r >= rows) continue;
                float vx = acc[mf][nf][half * 2 + 0] + bv.x;
                float vy = acc[mf][nf][half * 2 + 1] + bv.y;
                if (resid) {
                    float2 rz = *(const float2*)&resid[(size_t)r * HIDDEN + col];
                    vx += rz.x; vy += rz.y;
                }
                float2 o;
                o.x = vx > 0.f ? vx : 0.f;
                o.y = vy > 0.f ? vy : 0.f;
                *(float2*)&out[(size_t)r * HIDDEN + col] = o;
            }
        }
    }
}

// ---------------------------------------------------------------------------
// W pre-split: hi/lo bf16, transposed+padded to [NPAD][Kpad]
// ---------------------------------------------------------------------------
__global__ void split_w(const float* __restrict__ W, int K, int Kpad,
                        __nv_bfloat16* __restrict__ hi,
                        __nv_bfloat16* __restrict__ lo)
{
    int idx = blockIdx.x * blockDim.x + threadIdx.x;
    if (idx >= NPAD * Kpad) return;
    int n = idx / Kpad, k = idx % Kpad;
    float v = (n < HIDDEN && k < K) ? W[(size_t)k * HIDDEN + n] : 0.f;
    __nv_bfloat16 h = __float2bfloat16(v);
    hi[idx] = h;
    lo[idx] = __float2bfloat16(v - __bfloat162float(h));
}

// ---------------------------------------------------------------------------
__global__ void scatter_add(const float* __restrict__ h,
                            const int*   __restrict__ idx,
                            float* __restrict__ acc, int rows)
{
    int gid = blockIdx.x * blockDim.x + threadIdx.x;
    if (gid >= rows * 75) return;
    int e = gid / 75;
    int q = gid % 75;
    float4 v = ((const float4*)h)[(size_t)e * 75 + q];
    int d = idx[e];
    float* p = acc + (size_t)d * HIDDEN + q * 4;
    atomicAdd(p + 0, v.x);
    atomicAdd(p + 1, v.y);
    atomicAdd(p + 2, v.z);
    atomicAdd(p + 3, v.w);
}

__global__ void init_out(float* __restrict__ out, const float* __restrict__ feat)
{
    int gid = blockIdx.x * blockDim.x + threadIdx.x;
    if (gid >= N_MOL * OUT_COLS) return;
    int mol = gid / OUT_COLS;
    int c   = gid % OUT_COLS;
    out[gid] = (c < HIDDEN) ? 0.f : feat[mol * FEAT_DIM + (c - HIDDEN)];
}

__global__ void readout(const float* __restrict__ hv,
                        const int* __restrict__ mol_id,
                        float* __restrict__ out)
{
    int gid = blockIdx.x * blockDim.x + threadIdx.x;
    if (gid >= N_ATOMS * 75) return;
    int v = gid / 75;
    int q = gid % 75;
    float4 x = ((const float4*)hv)[(size_t)v * 75 + q];
    int mol = mol_id[v];
    float* p = out + (size_t)mol * OUT_COLS + q * 4;
    atomicAdd(p + 0, x.x);
    atomicAdd(p + 1, x.y);
    atomicAdd(p + 2, x.z);
    atomicAdd(p + 3, x.w);
}

// ---------------------------------------------------------------------------
extern "C" void kernel_launch(void* const* d_in, const int* in_sizes, int n_in,
                              void* d_out, int out_size)
{
    const float* x         = (const float*)d_in[0];
    const float* edge_attr = (const float*)d_in[1];
    const int*   edge_src  = (const int*)  d_in[2];
    const int*   edge_dst  = (const int*)  d_in[3];
    const int*   b2rev     = (const int*)  d_in[4];
    const int*   mol_id    = (const int*)  d_in[5];
    const float* features  = (const float*)d_in[6];
    const float* Wi        = (const float*)d_in[7];
    const float* bi        = (const float*)d_in[8];
    const float* Wm        = (const float*)d_in[9];
    const float* bm        = (const float*)d_in[10];
    const float* Wa        = (const float*)d_in[11];
    const float* ba        = (const float*)d_in[12];
    float* out = (float*)d_out;

    float *h0, *hA, *hB, *inc;
    cudaGetSymbolAddress((void**)&h0,  g_h0);
    cudaGetSymbolAddress((void**)&hA,  g_hA);
    cudaGetSymbolAddress((void**)&hB,  g_hB);
    cudaGetSymbolAddress((void**)&inc, g_inc);
    __nv_bfloat16 *wi_h, *wi_l, *wm_h, *wm_l, *wa_h, *wa_l;
    cudaGetSymbolAddress((void**)&wi_h, g_Wi_hi);
    cudaGetSymbolAddress((void**)&wi_l, g_Wi_lo);
    cudaGetSymbolAddress((void**)&wm_h, g_Wm_hi);
    cudaGetSymbolAddress((void**)&wm_l, g_Wm_lo);
    cudaGetSymbolAddress((void**)&wa_h, g_Wa_hi);
    cudaGetSymbolAddress((void**)&wa_l, g_Wa_lo);

    cudaFuncSetAttribute(mma_gemm, cudaFuncAttributeMaxDynamicSharedMemorySize,
                         SMEM_TOTAL);

    dim3 blk(256);
    dim3 mblk(512);
    dim3 gridE((NE + 127) / 128, 2);
    dim3 gridV((N_ATOMS + 127) / 128, 2);
    int scatE = (NE * 75 + 255) / 256;
    int scatV = (N_ATOMS * 75 + 255) / 256;

    // pre-split weights
    split_w<<<(NPAD * KPAD_I + 255) / 256, blk>>>(Wi, BOND_DIM + ATOM_DIM, KPAD_I, wi_h, wi_l);
    split_w<<<(NPAD * KPAD_M + 255) / 256, blk>>>(Wm, HIDDEN, KPAD_M, wm_h, wm_l);
    split_w<<<(NPAD * KPAD_A + 255) / 256, blk>>>(Wa, ATOM_DIM + HIDDEN, KPAD_A, wa_h, wa_l);

    // h0 = relu([edge_attr, x[src]] @ Wi + bi)
    mma_gemm<<<gridE, mblk, SMEM_TOTAL>>>(0, NE, BOND_DIM + ATOM_DIM, KPAD_I,
                                          edge_attr, x, edge_src, nullptr,
                                          wi_h, wi_l, bi, nullptr, h0);

    const float* hin = h0;
    float* houts[3] = { hA, hB, hA };
    for (int it = 0; it < DEPTH; it++) {
        float* hout = houts[it];
        cudaMemsetAsync(inc, 0, (size_t)N_ATOMS * HIDDEN * sizeof(float));
        scatter_add<<<scatE, blk>>>(hin, edge_dst, inc, NE);
        mma_gemm<<<gridE, mblk, SMEM_TOTAL>>>(3, NE, HIDDEN, KPAD_M,
                                              inc, hin, edge_src, b2rev,
                                              wm_h, wm_l, bm, h0, hout);
        hin = hout;
    }

    // m_v = segment_sum(h over edge_src)
    cudaMemsetAsync(inc, 0, (size_t)N_ATOMS * HIDDEN * sizeof(float));
    scatter_add<<<scatE, blk>>>(hin, edge_src, inc, NE);

    // h_v = relu([x, m_v] @ Wa + ba)
    mma_gemm<<<gridV, mblk, SMEM_TOTAL>>>(2, N_ATOMS, ATOM_DIM + HIDDEN, KPAD_A,
                                          x, inc, nullptr, nullptr,
                                          wa_h, wa_l, ba, nullptr, hB);

    // output: zeros | features, then molecule-sum readout
    init_out<<<(N_MOL * OUT_COLS + 255) / 256, blk>>>(out, features);
    readout<<<scatV, blk>>>(hB, mol_id, out);
}